// round 3
// baseline (speedup 1.0000x reference)
#include <cuda_runtime.h>

// loss = ||F^T F - S^T S||_F^2 * 2^-38,  F/S = [ch=64, hw=8192] channel-major.
// Kernel 1: 256 blocks each compute a 64x64 Gram-diff partial over 32 i-values
//           (f32x2 packed FMA, swizzled SMEM, 4x4 register tiles).
// Kernel 2: fused reduction (sum partials -> square -> sum) with a deterministic
//           last-block finish (int atomic counter only; all float sums fixed-order).

#define CH    64
#define HW    8192
#define IPB   32
#define NBLK  (HW / IPB)   // 256
#define GELEM (CH * CH)    // 4096

__device__ float g_partials[NBLK * GELEM];
__device__ float g_sq[32];
__device__ int   g_count;   // zero-initialized; reset by last block each call

__device__ __forceinline__ unsigned long long fma2(unsigned long long a,
                                                   unsigned long long b,
                                                   unsigned long long c) {
    unsigned long long d;
    asm("fma.rn.f32x2 %0, %1, %2, %3;" : "=l"(d) : "l"(a), "l"(b), "l"(c));
    return d;
}

__device__ __forceinline__ unsigned long long dup2(float x) {
    unsigned long long r;
    asm("mov.b64 %0, {%1, %1};" : "=l"(r) : "f"(x));
    return r;
}

__global__ void __launch_bounds__(256) gram_diff_kernel(const float* __restrict__ A,
                                                        const float* __restrict__ B) {
    // i-major rows of 64 floats; 16B group g at column 4*(g ^ (ii&15)).
    __shared__ __align__(16) float fsh[IPB][CH];
    __shared__ __align__(16) float ssh[IPB][CH];

    const int tid = threadIdx.x;
    const int i0  = blockIdx.x * IPB;

    // Stage 64c x 32i for both matrices (coalesced float4 global reads).
#pragma unroll
    for (int r = 0; r < 2; ++r) {
        int idx = r * 256 + tid;      // 0..511
        int c   = idx >> 3;           // 0..63
        int g   = idx & 7;            // float4 group along i (8 groups of 4 i)
        const float4 fv = *reinterpret_cast<const float4*>(A + (size_t)c * HW + i0 + 4 * g);
        const float4 sv = *reinterpret_cast<const float4*>(B + (size_t)c * HW + i0 + 4 * g);
        const int cg = c >> 2, cl = c & 3;
        float fvals[4] = {fv.x, fv.y, fv.z, fv.w};
        float svals[4] = {sv.x, sv.y, sv.z, sv.w};
#pragma unroll
        for (int k = 0; k < 4; ++k) {
            int ii  = 4 * g + k;
            int col = 4 * (cg ^ (ii & 15)) + cl;
            fsh[ii][col] = fvals[k];
            ssh[ii][col] = svals[k];
        }
    }
    __syncthreads();

    const int tx = tid & 15;
    const int ty = tid >> 4;

    // 4x4 tile as 4 rows x 2 packed-pair columns.
    unsigned long long acc[4][2];
#pragma unroll
    for (int a = 0; a < 4; ++a) { acc[a][0] = 0ull; acc[a][1] = 0ull; }

#pragma unroll
    for (int ii = 0; ii < IPB; ++ii) {
        const int sw = ii & 15;
        float4     fa4 = *reinterpret_cast<float4*>(&fsh[ii][4 * (ty ^ sw)]);
        ulonglong2 fb2 = *reinterpret_cast<ulonglong2*>(&fsh[ii][4 * (tx ^ sw)]);
        float4     sa4 = *reinterpret_cast<float4*>(&ssh[ii][4 * (ty ^ sw)]);
        ulonglong2 sb2 = *reinterpret_cast<ulonglong2*>(&ssh[ii][4 * (tx ^ sw)]);

        unsigned long long fd[4] = {dup2(fa4.x), dup2(fa4.y), dup2(fa4.z), dup2(fa4.w)};
        unsigned long long sd[4] = {dup2(-sa4.x), dup2(-sa4.y), dup2(-sa4.z), dup2(-sa4.w)};

#pragma unroll
        for (int a = 0; a < 4; ++a) {
            acc[a][0] = fma2(fd[a], fb2.x, acc[a][0]);
            acc[a][1] = fma2(fd[a], fb2.y, acc[a][1]);
            acc[a][0] = fma2(sd[a], sb2.x, acc[a][0]);
            acc[a][1] = fma2(sd[a], sb2.y, acc[a][1]);
        }
    }

    float* p = g_partials + (size_t)blockIdx.x * GELEM;
#pragma unroll
    for (int a = 0; a < 4; ++a) {
        float2 v0 = *reinterpret_cast<float2*>(&acc[a][0]);
        float2 v1 = *reinterpret_cast<float2*>(&acc[a][1]);
        float* row = p + (4 * ty + a) * CH + 4 * tx;
        row[0] = v0.x; row[1] = v0.y; row[2] = v1.x; row[3] = v1.y;
    }
}

__global__ void __launch_bounds__(128) reduce_kernel(float* __restrict__ out) {
    // 32 blocks x 128 threads: each thread owns one Gram entry.
    const int e = blockIdx.x * 128 + threadIdx.x;  // 0..4095
    float s = 0.0f;
#pragma unroll 8
    for (int b = 0; b < NBLK; ++b) s += g_partials[b * GELEM + e];
    float sq = s * s;

#pragma unroll
    for (int off = 16; off > 0; off >>= 1)
        sq += __shfl_down_sync(0xffffffffu, sq, off);

    __shared__ float wsum[4];
    __shared__ bool  is_last;
    if ((threadIdx.x & 31) == 0) wsum[threadIdx.x >> 5] = sq;
    __syncthreads();
    if (threadIdx.x == 0) {
        g_sq[blockIdx.x] = wsum[0] + wsum[1] + wsum[2] + wsum[3];
        __threadfence();
        is_last = (atomicAdd(&g_count, 1) == 31);
    }
    __syncthreads();

    if (is_last && threadIdx.x < 32) {
        float v = g_sq[threadIdx.x];
#pragma unroll
        for (int off = 16; off > 0; off >>= 1)
            v += __shfl_down_sync(0xffffffffu, v, off);
        if (threadIdx.x == 0) {
            out[0] = v * (1.0f / 274877906944.0f);  // 2^-38 exact
            g_count = 0;                            // reset for next graph replay
        }
    }
}

extern "C" void kernel_launch(void* const* d_in, const int* in_sizes, int n_in,
                              void* d_out, int out_size) {
    const float* A = (const float*)d_in[0];
    const float* B = (const float*)d_in[1];
    float* out = (float*)d_out;

    gram_diff_kernel<<<NBLK, 256>>>(A, B);
    reduce_kernel<<<32, 128>>>(out);
}

// round 4
// speedup vs baseline: 1.5551x; 1.5551x over previous
#include <cuda_runtime.h>

// loss = ||F^T F - S^T S||_F^2 * 2^-38,  F/S = [ch=64, hw=8192] channel-major.
// Single fused persistent kernel:
//   Phase 1: 256 blocks, each computes a 64x64 Gram-diff partial over 32 i's
//            (f32x2 packed FMA, padded/swizzled SMEM, 4x4 register tiles).
//   Grid barrier (all 256 blocks co-resident by construction).
//   Phase 2: same blocks reduce the partials (16 entries/block, fixed-order sums),
//            square, block-sum; deterministic last-block final fold.

#define CH    64
#define HW    8192
#define IPB   32
#define NBLK  (HW / IPB)   // 256
#define GELEM (CH * CH)    // 4096
#define PAD   68           // SMEM row stride in floats (bank-spread for the transpose)

__device__ float    g_partials[NBLK * GELEM];
__device__ float    g_bp[NBLK];
__device__ unsigned g_c1;   // grid-barrier counter (reset each call by last block)
__device__ unsigned g_c2;   // completion counter   (reset each call by last block)

__device__ __forceinline__ unsigned long long fma2(unsigned long long a,
                                                   unsigned long long b,
                                                   unsigned long long c) {
    unsigned long long d;
    asm("fma.rn.f32x2 %0, %1, %2, %3;" : "=l"(d) : "l"(a), "l"(b), "l"(c));
    return d;
}

__device__ __forceinline__ unsigned long long dup2(float x) {
    unsigned long long r;
    asm("mov.b64 %0, {%1, %1};" : "=l"(r) : "f"(x));
    return r;
}

__global__ void __launch_bounds__(256, 2) fused_loss_kernel(const float* __restrict__ A,
                                                            const float* __restrict__ B,
                                                            float* __restrict__ out) {
    __shared__ __align__(16) float fsh[IPB][PAD];
    __shared__ __align__(16) float ssh[IPB][PAD];
    __shared__ bool last;

    const int tid = threadIdx.x;
    const int bid = blockIdx.x;

    // ---------------- Phase 1: Gram-diff partial over i in [bid*IPB, +IPB) -------
    {
        const int i0 = bid * IPB;

        // Front-batched global loads (4x LDG.128 in flight), then transpose-store.
        int   cc[2], gg[2];
        float4 fv[2], sv[2];
#pragma unroll
        for (int r = 0; r < 2; ++r) {
            int idx = r * 256 + tid;   // 0..511
            cc[r] = idx >> 3;          // channel 0..63
            gg[r] = idx & 7;           // float4 group along i
            fv[r] = *reinterpret_cast<const float4*>(A + (size_t)cc[r] * HW + i0 + 4 * gg[r]);
            sv[r] = *reinterpret_cast<const float4*>(B + (size_t)cc[r] * HW + i0 + 4 * gg[r]);
        }
#pragma unroll
        for (int r = 0; r < 2; ++r) {
            const int cg = cc[r] >> 2, cl = cc[r] & 3;
            float fvals[4] = {fv[r].x, fv[r].y, fv[r].z, fv[r].w};
            float svals[4] = {sv[r].x, sv[r].y, sv[r].z, sv[r].w};
#pragma unroll
            for (int k = 0; k < 4; ++k) {
                int ii  = 4 * gg[r] + k;
                int col = 4 * (cg ^ (ii & 15)) + cl;
                fsh[ii][col] = fvals[k];
                ssh[ii][col] = svals[k];
            }
        }
        __syncthreads();

        const int tx = tid & 15;
        const int ty = tid >> 4;

        unsigned long long acc[4][2];
#pragma unroll
        for (int a = 0; a < 4; ++a) { acc[a][0] = 0ull; acc[a][1] = 0ull; }

#pragma unroll
        for (int ii = 0; ii < IPB; ++ii) {
            const int sw = ii & 15;
            float4     fa4 = *reinterpret_cast<float4*>(&fsh[ii][4 * (ty ^ sw)]);
            ulonglong2 fb2 = *reinterpret_cast<ulonglong2*>(&fsh[ii][4 * (tx ^ sw)]);
            float4     sa4 = *reinterpret_cast<float4*>(&ssh[ii][4 * (ty ^ sw)]);
            ulonglong2 sb2 = *reinterpret_cast<ulonglong2*>(&ssh[ii][4 * (tx ^ sw)]);

            unsigned long long fd[4] = {dup2(fa4.x), dup2(fa4.y), dup2(fa4.z), dup2(fa4.w)};
            unsigned long long sd[4] = {dup2(-sa4.x), dup2(-sa4.y), dup2(-sa4.z), dup2(-sa4.w)};

#pragma unroll
            for (int a = 0; a < 4; ++a) {
                acc[a][0] = fma2(fd[a], fb2.x, acc[a][0]);
                acc[a][1] = fma2(fd[a], fb2.y, acc[a][1]);
                acc[a][0] = fma2(sd[a], sb2.x, acc[a][0]);
                acc[a][1] = fma2(sd[a], sb2.y, acc[a][1]);
            }
        }

        float* p = g_partials + (size_t)bid * GELEM;
#pragma unroll
        for (int a = 0; a < 4; ++a) {
            float2 v0 = *reinterpret_cast<float2*>(&acc[a][0]);
            float2 v1 = *reinterpret_cast<float2*>(&acc[a][1]);
            float* row = p + (4 * ty + a) * CH + 4 * tx;
            row[0] = v0.x; row[1] = v0.y; row[2] = v1.x; row[3] = v1.y;
        }
    }

    // ---------------- Grid barrier (all NBLK blocks are co-resident) -------------
    __threadfence();
    __syncthreads();
    if (tid == 0) {
        atomicAdd(&g_c1, 1u);
        volatile unsigned* vc = &g_c1;
        while (*vc < NBLK) __nanosleep(32);
    }
    __syncthreads();
    __threadfence();

    // ---------------- Phase 2: reduce partials, square, sum ----------------------
    // Block handles 16 Gram entries; thread (grp, lane): grp = tid>>4 sums 16 b's.
    {
        const int lane = tid & 15;
        const int grp  = tid >> 4;          // 0..15
        const int e    = bid * 16 + lane;   // Gram entry 0..4095

        float s = 0.0f;
#pragma unroll
        for (int k = 0; k < 16; ++k)
            s += g_partials[(size_t)(grp * 16 + k) * GELEM + e];

        float (*sh)[16] = reinterpret_cast<float(*)[16]>(&fsh[0][0]);
        float* sqs      = &ssh[0][0];
        sh[grp][lane] = s;
        __syncthreads();
#pragma unroll
        for (int off = 8; off > 0; off >>= 1) {
            if (grp < off) sh[grp][lane] += sh[grp + off][lane];
            __syncthreads();
        }
        if (tid < 16) {
            float tot = sh[0][tid];
            sqs[tid] = tot * tot;
        }
        __syncthreads();

        if (tid == 0) {
            float bsum = 0.0f;
#pragma unroll
            for (int k = 0; k < 16; ++k) bsum += sqs[k];
            g_bp[bid] = bsum;
            __threadfence();
            last = (atomicAdd(&g_c2, 1u) == NBLK - 1);
        }
        __syncthreads();

        if (last && tid < 32) {
            __threadfence();
            volatile float* vb = g_bp;
            float v = 0.0f;
#pragma unroll
            for (int k = 0; k < 8; ++k) v += vb[tid + 32 * k];
#pragma unroll
            for (int off = 16; off > 0; off >>= 1)
                v += __shfl_down_sync(0xffffffffu, v, off);
            if (tid == 0) {
                out[0] = v * (1.0f / 274877906944.0f);  // * 2^-38 exact
                g_c1 = 0u;                              // reset for next replay
                g_c2 = 0u;
            }
        }
    }
}

extern "C" void kernel_launch(void* const* d_in, const int* in_sizes, int n_in,
                              void* d_out, int out_size) {
    const float* A = (const float*)d_in[0];  // input  [1,64,128,64] -> [64, 8192]
    const float* B = (const float*)d_in[1];  // target [1,64,128,64] -> [64, 8192]
    float* out = (float*)d_out;

    fused_loss_kernel<<<NBLK, 256>>>(A, B, out);
}